// round 10
// baseline (speedup 1.0000x reference)
#include <cuda_runtime.h>

#define NN 4096
#define EE 16384
#define DD 13
#define RR 128
#define NP 4
#define HOSTRIDE 132
#define PBLK 8
#define EPB  (EE / PBLK)
#define GCAP 2304
#define NBLK 152
#define NTHR 512

typedef unsigned long long u64;

__device__ int   g_groups[PBLK * GCAP];
__device__ int   g_cnt4[PBLK];
__device__ __align__(16) float g_nodes16[NN * 16];
__device__ __align__(16) float g_hoT[3 * NP * DD * HOSTRIDE];
__device__ int g_bar = 0, g_done = 0, g_exit = 0;

// smem layout (floats)
#define S_BP   0
#define S_BPB  (NP * DD * RR)
#define S_HO   (S_BPB + NP * RR)               // 7168, 16B aligned
#define S_HOB  (S_HO + 3 * NP * DD * HOSTRIDE)
#define S_TOT  (S_HOB + 3 * NP * DD)           // 27916 floats ~109.1 KiB

// ---------------- f32x2 packed helpers --------------------------------------
__device__ __forceinline__ u64 pk2(float lo, float hi) {
    u64 r; asm("mov.b64 %0,{%1,%2};" : "=l"(r) : "f"(lo), "f"(hi)); return r;
}
__device__ __forceinline__ u64 dup2(float v) {
    u64 r; asm("mov.b64 %0,{%1,%1};" : "=l"(r) : "f"(v)); return r;
}
__device__ __forceinline__ void up2(float& lo, float& hi, u64 v) {
    asm("mov.b64 {%0,%1},%2;" : "=f"(lo), "=f"(hi) : "l"(v));
}
__device__ __forceinline__ u64 fma2(u64 a, u64 b, u64 c) {
    u64 d; asm("fma.rn.f32x2 %0,%1,%2,%3;" : "=l"(d) : "l"(a), "l"(b), "l"(c)); return d;
}
__device__ __forceinline__ u64 mul2(u64 a, u64 b) {
    u64 d; asm("mul.rn.f32x2 %0,%1,%2;" : "=l"(d) : "l"(a), "l"(b)); return d;
}
__device__ __forceinline__ u64 add2(u64 a, u64 b) {
    u64 d; asm("add.rn.f32x2 %0,%1,%2;" : "=l"(d) : "l"(a), "l"(b)); return d;
}
__device__ __forceinline__ u64 relu2(u64 v) {
    float lo, hi; up2(lo, hi, v);
    return pk2(fmaxf(lo, 0.f), fmaxf(hi, 0.f));
}

// ---- packed warp reduction of 13 f32x2 streams ------------------------------
__device__ __forceinline__ u64 tree13p(u64* v, int lane) {
    {
        u64 o[13];
#pragma unroll
        for (int i = 0; i < 13; i++) o[i] = __shfl_xor_sync(0xffffffffu, v[i], 16);
        if (lane & 16) {
#pragma unroll
            for (int i = 0; i < 6; i++) v[i] = add2(v[i + 7], o[i + 7]);
        } else {
#pragma unroll
            for (int i = 0; i < 7; i++) v[i] = add2(v[i], o[i]);
        }
    }
    {
        u64 o[7];
#pragma unroll
        for (int i = 0; i < 7; i++) o[i] = __shfl_xor_sync(0xffffffffu, v[i], 8);
        if (!(lane & 16)) {
            if (lane & 8) { v[0] = add2(v[4], o[4]); v[1] = add2(v[5], o[5]); v[2] = add2(v[6], o[6]); }
            else { v[0] = add2(v[0], o[0]); v[1] = add2(v[1], o[1]); v[2] = add2(v[2], o[2]); v[3] = add2(v[3], o[3]); }
        } else {
            if (lane & 8) { v[0] = add2(v[3], o[3]); v[1] = add2(v[4], o[4]); v[2] = add2(v[5], o[5]); }
            else { v[0] = add2(v[0], o[0]); v[1] = add2(v[1], o[1]); v[2] = add2(v[2], o[2]); }
        }
    }
    {
        u64 o[4];
#pragma unroll
        for (int i = 0; i < 4; i++) o[i] = __shfl_xor_sync(0xffffffffu, v[i], 4);
        bool four = ((lane & 24) == 0);
        if (lane & 4) {
            v[0] = add2(v[2], o[2]);
            if (four) v[1] = add2(v[3], o[3]);
        } else {
            v[0] = add2(v[0], o[0]);
            v[1] = add2(v[1], o[1]);
        }
    }
    {
        u64 o0 = __shfl_xor_sync(0xffffffffu, v[0], 2);
        u64 o1 = __shfl_xor_sync(0xffffffffu, v[1], 2);
        v[0] = (lane & 2) ? add2(v[1], o1) : add2(v[0], o0);
    }
    {
        u64 o0 = __shfl_xor_sync(0xffffffffu, v[0], 1);
        v[0] = add2(v[0], o0);
    }
    return v[0];
}

__global__ void __launch_bounds__(NTHR, 1) k_fused(
    const float* __restrict__ nodes,
    const float* __restrict__ bp_params,
    const float* __restrict__ bp_bias,
    const float* __restrict__ ho_params,   // [3][NP][128][13]
    const float* __restrict__ ho_bias,
    const int*   __restrict__ edges,
    const int*   __restrict__ et,
    float*       __restrict__ out)
{
    extern __shared__ float sm[];
    const int tid  = threadIdx.x;
    const int lane = tid & 31;
    const int bid  = blockIdx.x;

    // ---- phase A (all blocks): fill bp parts of smem (no prep dependency) ---
    for (int i = tid; i < NP * DD * RR; i += NTHR) sm[S_BP + i] = bp_params[i];
    for (int i = tid; i < NP * RR; i += NTHR)      sm[S_BPB + i] = bp_bias[i];
    for (int i = tid; i < 3 * NP * DD; i += NTHR)  sm[S_HOB + i] = ho_bias[i];

    // ---- phase B (blocks 0..7): prep -----------------------------------------
    if (bid < PBLK) {
        // overlay prep scratch into the not-yet-filled S_HO region
        int*   hist    = (int*)(sm + S_HO);
        int*   bstart  = hist + 64;
        int*   cursor  = bstart + 64;
        int*   gb      = cursor + 64;
        short* sorted  = (short*)(gb + 64);
        unsigned char* keys = (unsigned char*)(sorted + EPB);
        unsigned char* skey = keys + EPB;
        const int base = bid * EPB;

        // zero output slice
        for (int i = tid; i < NN * DD / PBLK; i += NTHR)
            out[bid * (NN * DD / PBLK) + i] = 0.f;
        // padded node rows
        for (int i = tid; i < (NN / PBLK) * 16; i += NTHR) {
            int row = i >> 4, c = i & 15;
            int gr = bid * (NN / PBLK) + row;
            g_nodes16[gr * 16 + c] = (c < DD) ? nodes[gr * DD + c] : 0.f;
        }
        // transposed + padded HO weights (global), 1/8 slice per block
        {
            const int totalho = 3 * NP * RR * DD;   // 19968
            for (int i = bid * NTHR + tid; i < totalho; i += PBLK * NTHR) {
                int d  = i % DD;
                int rd = i / DD;
                int r  = rd & (RR - 1);
                int sp = rd >> 7;
                g_hoT[(sp * DD + d) * HOSTRIDE + r] = ho_params[i];
            }
        }
        // group buffer sentinel fill
        for (int i = tid; i < GCAP; i += NTHR) g_groups[bid * GCAP + i] = -1;

        if (tid < 64) hist[tid] = 0;
        __syncthreads();
        for (int i = tid; i < EPB; i += NTHR) {
            int e = base + i;
            int k = __ldg(et + e * 3) * 16 + __ldg(et + e * 3 + 1) * 4 + __ldg(et + e * 3 + 2);
            keys[i] = (unsigned char)k;
            atomicAdd(&hist[k], 1);
        }
        __syncthreads();
        if (tid == 0) {
            int run = 0, rg = 0;
            for (int k = 0; k < 64; k++) {
                bstart[k] = run; cursor[k] = run; run += hist[k];
                gb[k] = rg; rg += (hist[k] + 3) >> 2;
            }
            g_cnt4[bid] = rg;
        }
        __syncthreads();
        for (int i = tid; i < EPB; i += NTHR) {
            int k = keys[i];
            int pos = atomicAdd(&cursor[k], 1);
            sorted[pos] = (short)i;
            skey[pos] = (unsigned char)k;
        }
        __syncthreads();
        for (int i = tid; i < EPB; i += NTHR) {
            int k = skey[i];
            int r = i - bstart[k];
            g_groups[bid * GCAP + gb[k] * 4 + r] = base + (int)sorted[i];
        }
        __syncthreads();
    }

    // ---- device-wide barrier ------------------------------------------------
    __threadfence();
    __syncthreads();
    if (tid == 0) {
        int t = atomicAdd(&g_bar, 1);
        if (t == NBLK - 1) {
            atomicExch(&g_done, 1);
        } else {
            while (*(volatile int*)&g_done == 0) { }
        }
        __threadfence();
    }
    __syncthreads();

    // ---- fill HO smem from pre-transposed global (clean float4 copy) --------
    {
        const float4* src = reinterpret_cast<const float4*>(g_hoT);
        float4* dst = reinterpret_cast<float4*>(sm + S_HO);
        for (int i = tid; i < (3 * NP * DD * HOSTRIDE) / 4; i += NTHR) dst[i] = src[i];
    }
    __syncthreads();

    // ---- main loop ----------------------------------------------------------
    const int wid = bid * (NTHR >> 5) + (tid >> 5);
    const int nw  = NBLK * (NTHR >> 5);

    int pre[PBLK + 1];
    pre[0] = 0;
#pragma unroll
    for (int b = 0; b < PBLK; b++) pre[b + 1] = pre[b] + g_cnt4[b];
    const int total = pre[PBLK];

    const int b4 = (lane >> 4) & 1, b3 = (lane >> 3) & 1, b2 = (lane >> 2) & 1,
              b1 = (lane >> 1) & 1, b0 = lane & 1;
    const bool alive = (b0 == 0) && !(b1 && b2 && (b4 | b3));
    const int sid = 7 * b4 + (b4 ? 3 * b3 : 4 * b3) + 2 * b2 + b1;

#pragma unroll 1
    for (int u = wid; u < total; u += nw) {
        int bi = 0;
#pragma unroll
        for (int b = 1; b < PBLK; b++) bi += (u >= pre[b]);
        const int local = u - pre[bi];
        const int* gp = g_groups + bi * GCAP + local * 4;
        int ids[4];
#pragma unroll
        for (int b = 0; b < 4; b++) ids[b] = gp[b];
        int vmask = 1;
#pragma unroll
        for (int b = 1; b < 4; b++) {
            if (ids[b] >= 0) vmask |= (1 << b);
            else ids[b] = ids[0];
        }
        const int ty0 = __ldg(et + ids[0] * 3 + 0);
        const int ty1 = __ldg(et + ids[0] * 3 + 1);
        const int ty2 = __ldg(et + ids[0] * 3 + 2);
        const int ty[3] = {ty0, ty1, ty2};

        int nd[4][3];
#pragma unroll
        for (int b = 0; b < 4; b++)
#pragma unroll
            for (int s = 0; s < 3; s++)
                nd[b][s] = __ldg(edges + ids[b] * 3 + s);

        // ===== stage 1: packed accumulators over edge pairs ==================
        u64 t01[3][4], t23[3][4];
#pragma unroll
        for (int s = 0; s < 3; s++) {
            const float* wb = sm + S_BP + ty[s] * DD * RR;
            float4 bias = reinterpret_cast<const float4*>(sm + S_BPB + ty[s] * RR)[lane];
            u64 a01[4], a23[4];
            a01[0] = dup2(bias.x); a01[1] = dup2(bias.y);
            a01[2] = dup2(bias.z); a01[3] = dup2(bias.w);
            a23[0] = a01[0]; a23[1] = a01[1]; a23[2] = a01[2]; a23[3] = a01[3];
#pragma unroll
            for (int j = 0; j < 4; j++) {
                float4 rv0 = *reinterpret_cast<const float4*>(g_nodes16 + nd[0][s] * 16 + j * 4);
                float4 rv1 = *reinterpret_cast<const float4*>(g_nodes16 + nd[1][s] * 16 + j * 4);
                float4 rv2 = *reinterpret_cast<const float4*>(g_nodes16 + nd[2][s] * 16 + j * 4);
                float4 rv3 = *reinterpret_cast<const float4*>(g_nodes16 + nd[3][s] * 16 + j * 4);
                const int dmax = (j == 3) ? 1 : 4;
#pragma unroll
                for (int dc = 0; dc < dmax; dc++) {
                    const int d = j * 4 + dc;
                    float4 w = reinterpret_cast<const float4*>(wb + d * RR)[lane];
                    float r0 = (dc == 0) ? rv0.x : (dc == 1) ? rv0.y : (dc == 2) ? rv0.z : rv0.w;
                    float r1 = (dc == 0) ? rv1.x : (dc == 1) ? rv1.y : (dc == 2) ? rv1.z : rv1.w;
                    float r2 = (dc == 0) ? rv2.x : (dc == 1) ? rv2.y : (dc == 2) ? rv2.z : rv2.w;
                    float r3 = (dc == 0) ? rv3.x : (dc == 1) ? rv3.y : (dc == 2) ? rv3.z : rv3.w;
                    u64 rr01 = pk2(r0, r1), rr23 = pk2(r2, r3);
                    u64 wx = dup2(w.x), wy = dup2(w.y), wz = dup2(w.z), ww = dup2(w.w);
                    a01[0] = fma2(rr01, wx, a01[0]);
                    a01[1] = fma2(rr01, wy, a01[1]);
                    a01[2] = fma2(rr01, wz, a01[2]);
                    a01[3] = fma2(rr01, ww, a01[3]);
                    a23[0] = fma2(rr23, wx, a23[0]);
                    a23[1] = fma2(rr23, wy, a23[1]);
                    a23[2] = fma2(rr23, wz, a23[2]);
                    a23[3] = fma2(rr23, ww, a23[3]);
                }
            }
#pragma unroll
            for (int c = 0; c < 4; c++) {
                t01[s][c] = relu2(a01[c]);
                t23[s][c] = relu2(a23[c]);
            }
        }

        // ===== stage 2 =======================================================
#pragma unroll
        for (int s = 0; s < 3; s++) {
            const int jj = (s == 0) ? 1 : 0;
            const int kk = (s == 2) ? 1 : 2;
            u64 f01[4], f23[4];
#pragma unroll
            for (int c = 0; c < 4; c++) {
                f01[c] = mul2(t01[jj][c], t01[kk][c]);
                f23[c] = mul2(t23[jj][c], t23[kk][c]);
            }
            const float* wh = sm + S_HO + (s * NP + ty[s]) * DD * HOSTRIDE;
            const float* hb = sm + S_HOB + (s * NP + ty[s]) * DD;
            u64 ms01[DD], ms23[DD];
#pragma unroll
            for (int d = 0; d < DD; d++) {
                float4 w = reinterpret_cast<const float4*>(wh + d * HOSTRIDE)[lane];
                u64 wx = dup2(w.x), wy = dup2(w.y), wz = dup2(w.z), ww = dup2(w.w);
                u64 m0 = mul2(f01[0], wx);
                m0 = fma2(f01[1], wy, m0);
                m0 = fma2(f01[2], wz, m0);
                ms01[d] = fma2(f01[3], ww, m0);
                u64 m1 = mul2(f23[0], wx);
                m1 = fma2(f23[1], wy, m1);
                m1 = fma2(f23[2], wz, m1);
                ms23[d] = fma2(f23[3], ww, m1);
            }
            u64 r01 = tree13p(ms01, lane);
            u64 r23 = tree13p(ms23, lane);
            if (alive) {
                float bias = hb[sid];
                float lo, hi;
                up2(lo, hi, r01);
                atomicAdd(out + nd[0][s] * DD + sid, lo + bias);
                if (vmask & 2) atomicAdd(out + nd[1][s] * DD + sid, hi + bias);
                up2(lo, hi, r23);
                if (vmask & 4) atomicAdd(out + nd[2][s] * DD + sid, lo + bias);
                if (vmask & 8) atomicAdd(out + nd[3][s] * DD + sid, hi + bias);
            }
        }
    }

    // ---- epilogue: reset barrier state for the next (graph-replayed) launch -
    __syncthreads();
    if (tid == 0) {
        __threadfence();
        int t = atomicAdd(&g_exit, 1);
        if (t == NBLK - 1) {
            g_bar = 0; g_done = 0; g_exit = 0;
            __threadfence();
        }
    }
}

extern "C" void kernel_launch(void* const* d_in, const int* in_sizes, int n_in,
                              void* d_out, int out_size) {
    const float* nodes      = (const float*)d_in[0];
    const float* bp_params  = (const float*)d_in[1];
    const float* bp_bias    = (const float*)d_in[2];
    const float* ho_params  = (const float*)d_in[3];
    const float* ho_bias    = (const float*)d_in[4];
    const int*   edges      = (const int*)d_in[5];
    const int*   edge_types = (const int*)d_in[6];
    float* out = (float*)d_out;

    cudaFuncSetAttribute(k_fused, cudaFuncAttributeMaxDynamicSharedMemorySize, S_TOT * 4);
    k_fused<<<NBLK, NTHR, S_TOT * 4>>>(nodes, bp_params, bp_bias, ho_params, ho_bias,
                                       edges, edge_types, out);
}